// round 15
// baseline (speedup 1.0000x reference)
#include <cuda_runtime.h>

#define MODS   3
#define HEADS  4
#define HID    64
#define G      256
#define MAXN   50000
#define MAXE   250000
#define TOTDEG (9 * MAXN)
#define SCAN_BLOCKS ((TOTDEG + 2047) / 2048)   // 220

// ---------------- scratch (device globals; no allocation allowed) ----------------
static __device__ __align__(256) float d_h  [MODS * MAXN * HID];  // layer features
static __device__ __align__(256) float d_hp [MODS * MAXN * HID];  // projected features
static __device__ __align__(16) int   d_deg    [TOTDEG];
static __device__ __align__(16) int   d_scantmp[TOTDEG];
static __device__ int   d_bsum  [SCAN_BLOCKS];
static __device__ int   d_rowptr[9 * (MAXN + 1)];
static __device__ int   d_cursor[9 * MAXN];
static __device__ int   d_esrc  [9 * MAXE];
static __device__ int   d_start [MODS * G];
static __device__ float d_pool  [G * HID];
static __device__ float d_cnt   [G];

// ---------------- init ----------------
__global__ void k_init()
{
    int i = blockIdx.x * blockDim.x + threadIdx.x;
    if (i < TOTDEG)   d_deg[i] = 0;
    if (i < MODS * G) d_start[i] = 0x7fffffff;
    if (i < G * HID)  d_pool[i] = 0.f;
    if (i < G)        d_cnt[i] = 0.f;
    if (i < 9)        d_rowptr[i * (MAXN + 1) + MAXN] = MAXE;
}

__global__ void k_start_min(const int* __restrict__ b0, const int* __restrict__ b1,
                            const int* __restrict__ b2, int n)
{
    int i = blockIdx.x * blockDim.x + threadIdx.x;
    if (i >= n) return;
    const int* b = (blockIdx.y == 0) ? b0 : (blockIdx.y == 1) ? b1 : b2;
    atomicMin(&d_start[blockIdx.y * G + b[i]], i);
}

// ---------------- CSR build ----------------
__global__ void k_hist(const int* __restrict__ edges, int E)
{
    int rel = blockIdx.y;
    int e = blockIdx.x * blockDim.x + threadIdx.x;
    if (e >= E) return;
    int dN = edges[(size_t)rel * 2 * E + E + e];
    atomicAdd(&d_deg[rel * MAXN + dN], 1);
}

__global__ void k_scanA()
{
    __shared__ int sh[256];
    int t = threadIdx.x;
    int base = blockIdx.x * 2048 + t * 8;
    int v0 = 0, v1 = 0, v2 = 0, v3 = 0, v4 = 0, v5 = 0, v6 = 0, v7 = 0;
    if (base + 7 < TOTDEG) {
        int4 a = *(const int4*)&d_deg[base];
        int4 b = *(const int4*)&d_deg[base + 4];
        v0 = a.x; v1 = a.y; v2 = a.z; v3 = a.w;
        v4 = b.x; v5 = b.y; v6 = b.z; v7 = b.w;
    } else {
        if (base + 0 < TOTDEG) v0 = d_deg[base + 0];
        if (base + 1 < TOTDEG) v1 = d_deg[base + 1];
        if (base + 2 < TOTDEG) v2 = d_deg[base + 2];
        if (base + 3 < TOTDEG) v3 = d_deg[base + 3];
        if (base + 4 < TOTDEG) v4 = d_deg[base + 4];
        if (base + 5 < TOTDEG) v5 = d_deg[base + 5];
        if (base + 6 < TOTDEG) v6 = d_deg[base + 6];
        if (base + 7 < TOTDEG) v7 = d_deg[base + 7];
    }
    int tsum = v0 + v1 + v2 + v3 + v4 + v5 + v6 + v7;
    sh[t] = tsum;
    __syncthreads();
    for (int off = 1; off < 256; off <<= 1) {
        int v = (t >= off) ? sh[t - off] : 0;
        __syncthreads();
        sh[t] += v;
        __syncthreads();
    }
    int run = sh[t] - tsum;
    if (t == 255) d_bsum[blockIdx.x] = sh[255];
    int w;
    w = run; run += v0; if (base + 0 < TOTDEG) d_scantmp[base + 0] = w;
    w = run; run += v1; if (base + 1 < TOTDEG) d_scantmp[base + 1] = w;
    w = run; run += v2; if (base + 2 < TOTDEG) d_scantmp[base + 2] = w;
    w = run; run += v3; if (base + 3 < TOTDEG) d_scantmp[base + 3] = w;
    w = run; run += v4; if (base + 4 < TOTDEG) d_scantmp[base + 4] = w;
    w = run; run += v5; if (base + 5 < TOTDEG) d_scantmp[base + 5] = w;
    w = run; run += v6; if (base + 6 < TOTDEG) d_scantmp[base + 6] = w;
    w = run; run += v7; if (base + 7 < TOTDEG) d_scantmp[base + 7] = w;
}

__global__ void k_scanB()
{
    __shared__ int sh[256];
    int t = threadIdx.x;
    int v = (t < SCAN_BLOCKS) ? d_bsum[t] : 0;
    sh[t] = v;
    __syncthreads();
    for (int off = 1; off < 256; off <<= 1) {
        int x = (t >= off) ? sh[t - off] : 0;
        __syncthreads();
        sh[t] += x;
        __syncthreads();
    }
    if (t < SCAN_BLOCKS) d_bsum[t] = sh[t] - v;
}

__global__ void k_scanC()
{
    int idx = blockIdx.x * blockDim.x + threadIdx.x;
    if (idx >= TOTDEG) return;
    int val = d_scantmp[idx] + d_bsum[idx >> 11];
    int rel = idx / MAXN;
    int loc = idx - rel * MAXN;
    int r = val - rel * MAXE;
    d_rowptr[rel * (MAXN + 1) + loc] = r;
    d_cursor[rel * MAXN + loc] = r;
}

__global__ void k_scatter(const int* __restrict__ edges, int E)
{
    int rel = blockIdx.y;
    int e = blockIdx.x * blockDim.x + threadIdx.x;
    if (e >= E) return;
    const int* src = edges + (size_t)rel * 2 * E;
    int sN = src[e], dN = src[E + e];
    int pos = atomicAdd(&d_cursor[rel * MAXN + dN], 1);
    d_esrc[(size_t)rel * E + pos] = sN;
}

// ---------------- input projection + PE ----------------
// 256 thr, 32 nodes/block; thread = (ty node, tx 8-col group).
// Ws interleaved [c][half][tx] so each LDS.128 reads 128 contiguous bytes
// (1 wavefront, no bank conflict). Per k: 1 bcast LDS + 2 LDS.128 per 16 FMA.
template<int IN, int CK>
__global__ void k_inproj(const float* __restrict__ x, const float* __restrict__ W,
                         const float* __restrict__ b, const int* __restrict__ batch,
                         int mod, int n)
{
    __shared__ float  xs[32][IN];
    __shared__ float4 Ws[CK * 16];
    int tid = threadIdx.x;
    int node0 = blockIdx.x * 32;
    for (int idx = tid; idx < 32 * IN; idx += 256) {
        int r = idx / IN, k = idx - r * IN;
        int node = node0 + r;
        xs[r][k] = (node < n) ? x[(size_t)node * IN + k] : 0.f;
    }
    int ty = tid >> 3, tx = tid & 7;   // ty 0..31 (node), tx 0..7 (8 cols)
    int node = node0 + ty;

    const float4* __restrict__ W4 = (const float4*)W;
    float4 acc0 = ((const float4*)b)[tx * 2];
    float4 acc1 = ((const float4*)b)[tx * 2 + 1];
    const float* xa = xs[ty];

    const int NCHUNK = IN / CK;
    for (int ch = 0; ch < NCHUNK; ch++) {
        int k0 = ch * CK;
        __syncthreads();   // covers xs fill (first iter) / previous chunk compute
        for (int idx = tid; idx < CK * 16; idx += 256) {
            int c = idx >> 4, rem = idx & 15;
            int half = rem >> 3, t2 = rem & 7;
            Ws[idx] = W4[(size_t)(k0 + c) * 16 + t2 * 2 + half];
        }
        __syncthreads();
        #pragma unroll 5
        for (int c = 0; c < CK; c++) {
            float4 w0 = Ws[c * 16 + tx];
            float4 w1 = Ws[c * 16 + 8 + tx];
            float v = xa[k0 + c];
            acc0.x = fmaf(v, w0.x, acc0.x);
            acc0.y = fmaf(v, w0.y, acc0.y);
            acc0.z = fmaf(v, w0.z, acc0.z);
            acc0.w = fmaf(v, w0.w, acc0.w);
            acc1.x = fmaf(v, w1.x, acc1.x);
            acc1.y = fmaf(v, w1.y, acc1.y);
            acc1.z = fmaf(v, w1.z, acc1.z);
            acc1.w = fmaf(v, w1.w, acc1.w);
        }
    }

    // positional encoding (R1-proven math); cols tx*8 .. tx*8+7, kk = 4*tx+i
    if (node < n) {
        float pf = (float)(node - d_start[mod * G + batch[node]]);
        const float S = 9.210340371976184f / 64.0f;   // ln(1e4)/64
        float d0 = expf(-(float)(2 * (4 * tx + 0)) * S);
        float d1 = expf(-(float)(2 * (4 * tx + 1)) * S);
        float d2 = expf(-(float)(2 * (4 * tx + 2)) * S);
        float d3 = expf(-(float)(2 * (4 * tx + 3)) * S);
        float a0 = pf * d0, a1 = pf * d1, a2 = pf * d2, a3 = pf * d3;
        acc0.x += sinf(a0); acc0.y += cosf(a0);
        acc0.z += sinf(a1); acc0.w += cosf(a1);
        acc1.x += sinf(a2); acc1.y += cosf(a2);
        acc1.z += sinf(a3); acc1.w += cosf(a3);
        float4* dst = (float4*)(d_h + ((size_t)mod * n + node) * HID);
        dst[tx * 2]     = acc0;
        dst[tx * 2 + 1] = acc1;
    }
}

// ---------------- node projection: same conflict-free layout ----------------
__global__ void k_nodeproj(const float* __restrict__ Wl, const float* __restrict__ bl, int n)
{
    __shared__ float4 Ws[HID * 16];      // interleaved [k][half][tx], 16KB
    __shared__ float  xs[32][HID + 1];   // padded: rows in distinct banks
    int m = blockIdx.y;
    int tid = threadIdx.x;
    int node0 = blockIdx.x * 32;
    const float4* __restrict__ W4 = (const float4*)(Wl + m * HID * HID);
    for (int idx = tid; idx < HID * 16; idx += 256) {
        int k = idx >> 4, rem = idx & 15;
        int half = rem >> 3, t2 = rem & 7;
        Ws[idx] = W4[(size_t)k * 16 + t2 * 2 + half];
    }
    const float* __restrict__ src = d_h + (size_t)m * n * HID;
    for (int idx = tid; idx < 32 * HID; idx += 256) {
        int r = idx >> 6, k = idx & 63;
        int node = node0 + r;
        xs[r][k] = (node < n) ? src[(size_t)node * HID + k] : 0.f;
    }
    __syncthreads();
    int ty = tid >> 3, tx = tid & 7;
    int node = node0 + ty;

    float4 acc0 = ((const float4*)(bl + m * HID))[tx * 2];
    float4 acc1 = ((const float4*)(bl + m * HID))[tx * 2 + 1];
    const float* xa = xs[ty];
    #pragma unroll 4
    for (int k = 0; k < HID; k++) {
        float4 w0 = Ws[k * 16 + tx];
        float4 w1 = Ws[k * 16 + 8 + tx];
        float v = xa[k];
        acc0.x = fmaf(v, w0.x, acc0.x);
        acc0.y = fmaf(v, w0.y, acc0.y);
        acc0.z = fmaf(v, w0.z, acc0.z);
        acc0.w = fmaf(v, w0.w, acc0.w);
        acc1.x = fmaf(v, w1.x, acc1.x);
        acc1.y = fmaf(v, w1.y, acc1.y);
        acc1.z = fmaf(v, w1.z, acc1.z);
        acc1.w = fmaf(v, w1.w, acc1.w);
    }
    if (node < n) {
        float4* dst = (float4*)(d_hp + ((size_t)m * n + node) * HID);
        dst[tx * 2]     = acc0;
        dst[tx * 2 + 1] = acc1;
    }
}

// ---------------- GAT layer: warp per dst; 4 edges in flight (MLP=4) ----------------
__global__ void k_gat(const float* __restrict__ attL, int n)
{
    int wid = threadIdx.x >> 5, lane = threadIdx.x & 31;
    int dst = blockIdx.x * 8 + wid;
    if (dst >= n) return;
    int j = blockIdx.y;
    int l2 = lane * 2;

    float2 hd = *(const float2*)&d_hp[((size_t)j * n + dst) * HID + l2];
    float accx = 0.f, accy = 0.f;

    for (int i = 0; i < MODS; i++) {
        int rel = i * 3 + j;
        int rs = d_rowptr[rel * (MAXN + 1) + dst];
        int re = d_rowptr[rel * (MAXN + 1) + dst + 1];
        if (rs == re) continue;
        float2 a2 = *(const float2*)&attL[rel * HID + l2];
        const float* __restrict__ hpB = d_hp + (size_t)i * n * HID;
        const int* __restrict__ es = d_esrc + (size_t)rel * MAXE;

        float s = 0.f, ax = 0.f, ay = 0.f;
        for (int c0 = rs; c0 < re; c0 += 32) {
            int idx = c0 + lane;
            int my = es[idx < re ? idx : re - 1];   // clamped: always a valid src
            int cnt = min(32, re - c0);
            for (int q = 0; q < cnt; q += 4) {
                int s0 = __shfl_sync(0xffffffffu, my, q);
                int s1 = __shfl_sync(0xffffffffu, my, q + 1);
                int s2 = __shfl_sync(0xffffffffu, my, q + 2);
                int s3 = __shfl_sync(0xffffffffu, my, q + 3);
                bool v1 = (q + 1 < cnt), v2 = (q + 2 < cnt), v3 = (q + 3 < cnt);
                float2 h0 = *(const float2*)&hpB[(size_t)s0 * HID + l2];
                float2 h1 = *(const float2*)&hpB[(size_t)s1 * HID + l2];
                float2 h2 = *(const float2*)&hpB[(size_t)s2 * HID + l2];
                float2 h3 = *(const float2*)&hpB[(size_t)s3 * HID + l2];

                float z, t0, t1, t2, t3;
                z = h0.x + hd.x; z = fmaxf(z, 0.2f * z); t0  = z * a2.x;
                z = h0.y + hd.y; z = fmaxf(z, 0.2f * z); t0 += z * a2.y;
                z = h1.x + hd.x; z = fmaxf(z, 0.2f * z); t1  = z * a2.x;
                z = h1.y + hd.y; z = fmaxf(z, 0.2f * z); t1 += z * a2.y;
                z = h2.x + hd.x; z = fmaxf(z, 0.2f * z); t2  = z * a2.x;
                z = h2.y + hd.y; z = fmaxf(z, 0.2f * z); t2 += z * a2.y;
                z = h3.x + hd.x; z = fmaxf(z, 0.2f * z); t3  = z * a2.x;
                z = h3.y + hd.y; z = fmaxf(z, 0.2f * z); t3 += z * a2.y;

                t0 += __shfl_xor_sync(0xffffffffu, t0, 1);
                t1 += __shfl_xor_sync(0xffffffffu, t1, 1);
                t2 += __shfl_xor_sync(0xffffffffu, t2, 1);
                t3 += __shfl_xor_sync(0xffffffffu, t3, 1);
                t0 += __shfl_xor_sync(0xffffffffu, t0, 2);
                t1 += __shfl_xor_sync(0xffffffffu, t1, 2);
                t2 += __shfl_xor_sync(0xffffffffu, t2, 2);
                t3 += __shfl_xor_sync(0xffffffffu, t3, 2);
                t0 += __shfl_xor_sync(0xffffffffu, t0, 4);
                t1 += __shfl_xor_sync(0xffffffffu, t1, 4);
                t2 += __shfl_xor_sync(0xffffffffu, t2, 4);
                t3 += __shfl_xor_sync(0xffffffffu, t3, 4);

                float e0 = __expf(t0);
                float e1 = v1 ? __expf(t1) : 0.f;
                float e2 = v2 ? __expf(t2) : 0.f;
                float e3 = v3 ? __expf(t3) : 0.f;

                s += (e0 + e1) + (e2 + e3);
                ax = fmaf(e0, h0.x, fmaf(e1, h1.x, fmaf(e2, h2.x, fmaf(e3, h3.x, ax))));
                ay = fmaf(e0, h0.y, fmaf(e1, h1.y, fmaf(e2, h2.y, fmaf(e3, h3.y, ay))));
            }
        }
        float inv_s = 1.f / s;
        accx = fmaf(ax, inv_s, accx);
        accy = fmaf(ay, inv_s, accy);
    }

    float ox = accx * (1.f / 3.f); ox = ox > 0.f ? ox : 0.f;
    float oy = accy * (1.f / 3.f); oy = oy > 0.f ? oy : 0.f;
    float2 o = {ox, oy};
    *(float2*)&d_h[((size_t)j * n + dst) * HID + l2] = o;
}

// ---------------- pooling (R1-proven form) ----------------
__global__ void k_pool(const int* __restrict__ b0, const int* __restrict__ b1,
                       const int* __restrict__ b2, int n)
{
    const int CH = 128;
    int m = blockIdx.y;
    const int* batch = (m == 0) ? b0 : (m == 1) ? b1 : b2;
    const float* h = d_h + (size_t)m * n * HID;
    int i0 = blockIdx.x * CH;
    int c = threadIdx.x;
    int end = min(i0 + CH, n);
    float acc = 0.f; int cur = -1; int run = 0;
    for (int i = i0; i < end; i++) {
        int bg = batch[i];
        if (bg != cur) {
            if (cur >= 0) {
                atomicAdd(&d_pool[cur * HID + c], acc);
                if (c == 0) atomicAdd(&d_cnt[cur], (float)run);
            }
            cur = bg; acc = 0.f; run = 0;
        }
        acc += h[(size_t)i * HID + c];
        run++;
    }
    if (cur >= 0) {
        atomicAdd(&d_pool[cur * HID + c], acc);
        if (c == 0) atomicAdd(&d_cnt[cur], (float)run);
    }
}

// ---------------- readout MLP (R1-proven form) ----------------
__global__ void k_mlp(const float* __restrict__ Wf1, const float* __restrict__ bf1,
                      const float* __restrict__ Wf2, const float* __restrict__ bf2,
                      const float* __restrict__ Wf3, const float* __restrict__ bf3,
                      float* __restrict__ out)
{
    int g = threadIdx.x; // 256 threads, 1 block
    float inv = 1.f / fmaxf(d_cnt[g], 1.f);
    float y1[16];
    #pragma unroll
    for (int j = 0; j < 16; j++) y1[j] = bf1[j];
    for (int k = 0; k < HID; k++) {
        float v = d_pool[g * HID + k] * inv;
        #pragma unroll
        for (int j = 0; j < 16; j++) y1[j] = fmaf(v, Wf1[k * 16 + j], y1[j]);
    }
    float y2[16];
    #pragma unroll
    for (int j = 0; j < 16; j++) y2[j] = bf2[j];
    #pragma unroll
    for (int k = 0; k < 16; k++) {
        float v = y1[k] > 0.f ? y1[k] : 0.f;
        #pragma unroll
        for (int j = 0; j < 16; j++) y2[j] = fmaf(v, Wf2[k * 16 + j], y2[j]);
    }
    float o = bf3[0];
    #pragma unroll
    for (int j = 0; j < 16; j++) {
        float v = y2[j] > 0.f ? y2[j] : 0.f;
        o = fmaf(v, Wf3[j], o);
    }
    out[g] = o;
}

// ---------------- host launcher ----------------
extern "C" void kernel_launch(void* const* d_in, const int* in_sizes, int n_in,
                              void* d_out, int out_size)
{
    const float *x_text = 0, *x_audio = 0, *x_video = 0;
    const float *Wi_text = 0, *Wi_audio = 0, *Wi_video = 0;
    const float *bi[3] = {0, 0, 0};
    const float *Wn = 0, *bn = 0, *att = 0;
    const float *Wf1 = 0, *bf1 = 0, *Wf2 = 0, *bf2 = 0, *Wf3 = 0, *bf3 = 0;
    const int *batch[3] = {0, 0, 0};
    const int *edges = 0;
    int nb = 0, nbi = 0, n16 = 0;

    for (int i = 0; i < n_in; i++) {
        int s = in_sizes[i];
        const void* p = d_in[i];
        if      (s == 50000 * 300) x_text  = (const float*)p;
        else if (s == 50000 * 74)  x_audio = (const float*)p;
        else if (s == 50000 * 35)  x_video = (const float*)p;
        else if (s == 50000)       { if (nb < 3) batch[nb++] = (const int*)p; }
        else if (s == 9 * 2 * 250000) edges = (const int*)p;
        else if (s == 300 * 64)    Wi_text  = (const float*)p;
        else if (s == 74 * 64)     Wi_audio = (const float*)p;
        else if (s == 35 * 64)     Wi_video = (const float*)p;
        else if (s == 64)          { if (nbi < 3) bi[nbi++] = (const float*)p; }
        else if (s == 2 * 3 * 64 * 64) Wn = (const float*)p;
        else if (s == 2 * 3 * 64)  bn  = (const float*)p;
        else if (s == 2 * 9 * 64)  att = (const float*)p;
        else if (s == 64 * 16)     Wf1 = (const float*)p;
        else if (s == 16)          { if (n16 == 0) bf1 = (const float*)p;
                                     else if (n16 == 1) bf2 = (const float*)p;
                                     else Wf3 = (const float*)p; n16++; }
        else if (s == 16 * 16)     Wf2 = (const float*)p;
        else if (s == 1)           bf3 = (const float*)p;
    }

    const int n = MAXN, E = MAXE;
    const int nblk32 = (n + 31) / 32;

    // Keep k_inproj<300> in the ncu capture slot (4th launch) to verify the delta.
    k_init<<<(TOTDEG + 255) / 256, 256>>>();                                          // 1
    k_start_min<<<dim3((n + 255) / 256, 3), 256>>>(batch[0], batch[1], batch[2], n);  // 2
    k_hist<<<dim3((E + 255) / 256, 9), 256>>>(edges, E);                              // 3
    k_inproj<300, 30><<<nblk32, 256>>>(x_text,  Wi_text,  bi[0], batch[0], 0, n);     // 4 <- ncu slot
    k_inproj<74, 37> <<<nblk32, 256>>>(x_audio, Wi_audio, bi[1], batch[1], 1, n);     // 5
    k_inproj<35, 35> <<<nblk32, 256>>>(x_video, Wi_video, bi[2], batch[2], 2, n);     // 6

    // CSR build (independent of projections)
    k_scanA<<<SCAN_BLOCKS, 256>>>();
    k_scanB<<<1, 256>>>();
    k_scanC<<<(TOTDEG + 255) / 256, 256>>>();
    k_scatter<<<dim3((E + 255) / 256, 9), 256>>>(edges, E);

    // GAT layers
    for (int l = 0; l < 2; l++) {
        k_nodeproj<<<dim3(nblk32, 3), 256>>>(Wn + (size_t)l * 3 * HID * HID,
                                             bn + (size_t)l * 3 * HID, n);
        k_gat<<<dim3((n + 7) / 8, 3), 256>>>(att + (size_t)l * 9 * HID, n);
    }

    // pooling + MLP head
    k_pool<<<dim3((n + 127) / 128, 3), 64>>>(batch[0], batch[1], batch[2], n);
    k_mlp<<<1, 256>>>(Wf1, bf1, Wf2, bf2, Wf3, bf3, (float*)d_out);
}

// round 16
// speedup vs baseline: 1.1056x; 1.1056x over previous
#include <cuda_runtime.h>

#define MODS   3
#define HEADS  4
#define HID    64
#define G      256
#define MAXN   50000
#define MAXE   250000
#define TOTDEG (9 * MAXN)
#define SCAN_BLOCKS ((TOTDEG + 2047) / 2048)   // 220

// ---------------- scratch (device globals; no allocation allowed) ----------------
static __device__ __align__(256) float d_h  [MODS * MAXN * HID];  // layer features
static __device__ __align__(256) float d_hp [MODS * MAXN * HID];  // projected features
static __device__ __align__(16) int   d_deg    [TOTDEG];
static __device__ __align__(16) int   d_scantmp[TOTDEG];
static __device__ int   d_bsum  [SCAN_BLOCKS];
static __device__ int   d_rowptr[9 * (MAXN + 1)];
static __device__ int   d_cursor[9 * MAXN];
static __device__ int   d_esrc  [9 * MAXE];
static __device__ int   d_start [MODS * G];
static __device__ float d_pool  [G * HID];
static __device__ float d_cnt   [G];

// ---------------- init ----------------
__global__ void k_init()
{
    int i = blockIdx.x * blockDim.x + threadIdx.x;
    if (i < TOTDEG)   d_deg[i] = 0;
    if (i < MODS * G) d_start[i] = 0x7fffffff;
    if (i < G * HID)  d_pool[i] = 0.f;
    if (i < G)        d_cnt[i] = 0.f;
    if (i < 9)        d_rowptr[i * (MAXN + 1) + MAXN] = MAXE;
}

__global__ void k_start_min(const int* __restrict__ b0, const int* __restrict__ b1,
                            const int* __restrict__ b2, int n)
{
    int i = blockIdx.x * blockDim.x + threadIdx.x;
    if (i >= n) return;
    const int* b = (blockIdx.y == 0) ? b0 : (blockIdx.y == 1) ? b1 : b2;
    atomicMin(&d_start[blockIdx.y * G + b[i]], i);
}

// ---------------- CSR build ----------------
__global__ void k_hist(const int* __restrict__ edges, int E)
{
    int rel = blockIdx.y;
    int e = blockIdx.x * blockDim.x + threadIdx.x;
    if (e >= E) return;
    int dN = edges[(size_t)rel * 2 * E + E + e];
    atomicAdd(&d_deg[rel * MAXN + dN], 1);
}

__global__ void k_scanA()
{
    __shared__ int sh[256];
    int t = threadIdx.x;
    int base = blockIdx.x * 2048 + t * 8;
    int v0 = 0, v1 = 0, v2 = 0, v3 = 0, v4 = 0, v5 = 0, v6 = 0, v7 = 0;
    if (base + 7 < TOTDEG) {
        int4 a = *(const int4*)&d_deg[base];
        int4 b = *(const int4*)&d_deg[base + 4];
        v0 = a.x; v1 = a.y; v2 = a.z; v3 = a.w;
        v4 = b.x; v5 = b.y; v6 = b.z; v7 = b.w;
    } else {
        if (base + 0 < TOTDEG) v0 = d_deg[base + 0];
        if (base + 1 < TOTDEG) v1 = d_deg[base + 1];
        if (base + 2 < TOTDEG) v2 = d_deg[base + 2];
        if (base + 3 < TOTDEG) v3 = d_deg[base + 3];
        if (base + 4 < TOTDEG) v4 = d_deg[base + 4];
        if (base + 5 < TOTDEG) v5 = d_deg[base + 5];
        if (base + 6 < TOTDEG) v6 = d_deg[base + 6];
        if (base + 7 < TOTDEG) v7 = d_deg[base + 7];
    }
    int tsum = v0 + v1 + v2 + v3 + v4 + v5 + v6 + v7;
    sh[t] = tsum;
    __syncthreads();
    for (int off = 1; off < 256; off <<= 1) {
        int v = (t >= off) ? sh[t - off] : 0;
        __syncthreads();
        sh[t] += v;
        __syncthreads();
    }
    int run = sh[t] - tsum;
    if (t == 255) d_bsum[blockIdx.x] = sh[255];
    int w;
    w = run; run += v0; if (base + 0 < TOTDEG) d_scantmp[base + 0] = w;
    w = run; run += v1; if (base + 1 < TOTDEG) d_scantmp[base + 1] = w;
    w = run; run += v2; if (base + 2 < TOTDEG) d_scantmp[base + 2] = w;
    w = run; run += v3; if (base + 3 < TOTDEG) d_scantmp[base + 3] = w;
    w = run; run += v4; if (base + 4 < TOTDEG) d_scantmp[base + 4] = w;
    w = run; run += v5; if (base + 5 < TOTDEG) d_scantmp[base + 5] = w;
    w = run; run += v6; if (base + 6 < TOTDEG) d_scantmp[base + 6] = w;
    w = run; run += v7; if (base + 7 < TOTDEG) d_scantmp[base + 7] = w;
}

__global__ void k_scanB()
{
    __shared__ int sh[256];
    int t = threadIdx.x;
    int v = (t < SCAN_BLOCKS) ? d_bsum[t] : 0;
    sh[t] = v;
    __syncthreads();
    for (int off = 1; off < 256; off <<= 1) {
        int x = (t >= off) ? sh[t - off] : 0;
        __syncthreads();
        sh[t] += x;
        __syncthreads();
    }
    if (t < SCAN_BLOCKS) d_bsum[t] = sh[t] - v;
}

__global__ void k_scanC()
{
    int idx = blockIdx.x * blockDim.x + threadIdx.x;
    if (idx >= TOTDEG) return;
    int val = d_scantmp[idx] + d_bsum[idx >> 11];
    int rel = idx / MAXN;
    int loc = idx - rel * MAXN;
    int r = val - rel * MAXE;
    d_rowptr[rel * (MAXN + 1) + loc] = r;
    d_cursor[rel * MAXN + loc] = r;
}

__global__ void k_scatter(const int* __restrict__ edges, int E)
{
    int rel = blockIdx.y;
    int e = blockIdx.x * blockDim.x + threadIdx.x;
    if (e >= E) return;
    const int* src = edges + (size_t)rel * 2 * E;
    int sN = src[e], dN = src[E + e];
    int pos = atomicAdd(&d_cursor[rel * MAXN + dN], 1);
    d_esrc[(size_t)rel * E + pos] = sN;
}

// ---------------- input projection + PE: 128 thr, 32 nodes/block, 4 nodes x 4 cols/thread ----------------
// Minimizes smem bytes/FMA: per k = 4 scalar x-loads + 1 LDS.128 w per 16 FMA = 2 B/FMA
// (R14 was 3 B/FMA, R15's 8-col layout was 4.5 B/FMA — measured L1-bound scaling).
template<int IN, int CK>
__global__ void k_inproj(const float* __restrict__ x, const float* __restrict__ W,
                         const float* __restrict__ b, const int* __restrict__ batch,
                         int mod, int n)
{
    __shared__ float  xs[32][IN];
    __shared__ float4 Ws[CK * 16];
    int tid = threadIdx.x;   // 128 threads
    int node0 = blockIdx.x * 32;
    for (int idx = tid; idx < 32 * IN; idx += 128) {
        int r = idx / IN, k = idx - r * IN;
        int node = node0 + r;
        xs[r][k] = (node < n) ? x[(size_t)node * IN + k] : 0.f;
    }
    int ty = tid >> 4, tx = tid & 15;   // ty 0..7 (4 nodes each), tx 0..15 (4 cols)
    int nbase = node0 + ty * 4;

    const float4* __restrict__ W4 = (const float4*)W;
    float4 bb = ((const float4*)b)[tx];
    float4 acc0 = bb, acc1 = bb, acc2 = bb, acc3 = bb;
    const float* x0 = xs[ty * 4 + 0];
    const float* x1 = xs[ty * 4 + 1];
    const float* x2 = xs[ty * 4 + 2];
    const float* x3 = xs[ty * 4 + 3];

    const int NCHUNK = IN / CK;
    for (int ch = 0; ch < NCHUNK; ch++) {
        int k0 = ch * CK;
        __syncthreads();   // covers xs fill (first iter) / previous chunk compute
        for (int idx = tid; idx < CK * 16; idx += 128)
            Ws[idx] = W4[(size_t)k0 * 16 + idx];
        __syncthreads();
        #pragma unroll 5
        for (int c = 0; c < CK; c++) {
            float4 wv = Ws[c * 16 + tx];
            float v0 = x0[k0 + c], v1 = x1[k0 + c], v2 = x2[k0 + c], v3 = x3[k0 + c];
            acc0.x = fmaf(v0, wv.x, acc0.x); acc0.y = fmaf(v0, wv.y, acc0.y);
            acc0.z = fmaf(v0, wv.z, acc0.z); acc0.w = fmaf(v0, wv.w, acc0.w);
            acc1.x = fmaf(v1, wv.x, acc1.x); acc1.y = fmaf(v1, wv.y, acc1.y);
            acc1.z = fmaf(v1, wv.z, acc1.z); acc1.w = fmaf(v1, wv.w, acc1.w);
            acc2.x = fmaf(v2, wv.x, acc2.x); acc2.y = fmaf(v2, wv.y, acc2.y);
            acc2.z = fmaf(v2, wv.z, acc2.z); acc2.w = fmaf(v2, wv.w, acc2.w);
            acc3.x = fmaf(v3, wv.x, acc3.x); acc3.y = fmaf(v3, wv.y, acc3.y);
            acc3.z = fmaf(v3, wv.z, acc3.z); acc3.w = fmaf(v3, wv.w, acc3.w);
        }
    }

    // positional encoding (R1-proven math); cols tx*4 .. tx*4+3 -> kk = 2tx, 2tx+1
    float div0 = expf(-(float)(2 * (2 * tx)) * (9.210340371976184f / 64.0f));
    float div1 = expf(-(float)(2 * (2 * tx + 1)) * (9.210340371976184f / 64.0f));
    #pragma unroll
    for (int q = 0; q < 4; q++) {
        int node = nbase + q;
        if (node >= n) break;
        float4 acc = (q == 0) ? acc0 : (q == 1) ? acc1 : (q == 2) ? acc2 : acc3;
        float pf = (float)(node - d_start[mod * G + batch[node]]);
        float a0 = pf * div0, a1 = pf * div1;
        acc.x += sinf(a0); acc.y += cosf(a0);
        acc.z += sinf(a1); acc.w += cosf(a1);
        ((float4*)(d_h + ((size_t)mod * n + node) * HID))[tx] = acc;
    }
}

// ---------------- node projection: W staged in smem, 2 nodes x 4 cols per thread (R8/R14-proven) ----------------
__global__ void k_nodeproj(const float* __restrict__ Wl, const float* __restrict__ bl, int n)
{
    __shared__ float4 Ws[HID * 16];     // 16KB
    __shared__ float  xs[32][HID];      // 8KB
    int m = blockIdx.y;
    int tid = threadIdx.x;
    int node0 = blockIdx.x * 32;
    const float4* __restrict__ W4 = (const float4*)(Wl + m * HID * HID);
    for (int idx = tid; idx < HID * 16; idx += 256) Ws[idx] = W4[idx];
    const float* __restrict__ src = d_h + (size_t)m * n * HID;
    for (int idx = tid; idx < 32 * HID; idx += 256) {
        int r = idx >> 6, k = idx & 63;
        int node = node0 + r;
        xs[r][k] = (node < n) ? src[(size_t)node * HID + k] : 0.f;
    }
    __syncthreads();
    int ty = tid >> 4, tx = tid & 15;
    int na = node0 + ty * 2, nb = na + 1;

    float4 bb = ((const float4*)(bl + m * HID))[tx];
    float4 acc0 = bb, acc1 = bb;
    const float* xa = xs[ty * 2];
    const float* xb = xs[ty * 2 + 1];
    #pragma unroll 4
    for (int k = 0; k < HID; k++) {
        float4 wv = Ws[k * 16 + tx];
        float va = xa[k], vb = xb[k];
        acc0.x = fmaf(va, wv.x, acc0.x);
        acc0.y = fmaf(va, wv.y, acc0.y);
        acc0.z = fmaf(va, wv.z, acc0.z);
        acc0.w = fmaf(va, wv.w, acc0.w);
        acc1.x = fmaf(vb, wv.x, acc1.x);
        acc1.y = fmaf(vb, wv.y, acc1.y);
        acc1.z = fmaf(vb, wv.z, acc1.z);
        acc1.w = fmaf(vb, wv.w, acc1.w);
    }
    if (na < n) ((float4*)(d_hp + ((size_t)m * n + na) * HID))[tx] = acc0;
    if (nb < n) ((float4*)(d_hp + ((size_t)m * n + nb) * HID))[tx] = acc1;
}

// ---------------- GAT layer: warp per dst; 4 edges in flight (MLP=4) ----------------
__global__ void k_gat(const float* __restrict__ attL, int n)
{
    int wid = threadIdx.x >> 5, lane = threadIdx.x & 31;
    int dst = blockIdx.x * 8 + wid;
    if (dst >= n) return;
    int j = blockIdx.y;
    int l2 = lane * 2;

    float2 hd = *(const float2*)&d_hp[((size_t)j * n + dst) * HID + l2];
    float accx = 0.f, accy = 0.f;

    for (int i = 0; i < MODS; i++) {
        int rel = i * 3 + j;
        int rs = d_rowptr[rel * (MAXN + 1) + dst];
        int re = d_rowptr[rel * (MAXN + 1) + dst + 1];
        if (rs == re) continue;
        float2 a2 = *(const float2*)&attL[rel * HID + l2];
        const float* __restrict__ hpB = d_hp + (size_t)i * n * HID;
        const int* __restrict__ es = d_esrc + (size_t)rel * MAXE;

        float s = 0.f, ax = 0.f, ay = 0.f;
        for (int c0 = rs; c0 < re; c0 += 32) {
            int idx = c0 + lane;
            int my = es[idx < re ? idx : re - 1];   // clamped: always a valid src
            int cnt = min(32, re - c0);
            for (int q = 0; q < cnt; q += 4) {
                int s0 = __shfl_sync(0xffffffffu, my, q);
                int s1 = __shfl_sync(0xffffffffu, my, q + 1);
                int s2 = __shfl_sync(0xffffffffu, my, q + 2);
                int s3 = __shfl_sync(0xffffffffu, my, q + 3);
                bool v1 = (q + 1 < cnt), v2 = (q + 2 < cnt), v3 = (q + 3 < cnt);
                float2 h0 = *(const float2*)&hpB[(size_t)s0 * HID + l2];
                float2 h1 = *(const float2*)&hpB[(size_t)s1 * HID + l2];
                float2 h2 = *(const float2*)&hpB[(size_t)s2 * HID + l2];
                float2 h3 = *(const float2*)&hpB[(size_t)s3 * HID + l2];

                float z, t0, t1, t2, t3;
                z = h0.x + hd.x; z = fmaxf(z, 0.2f * z); t0  = z * a2.x;
                z = h0.y + hd.y; z = fmaxf(z, 0.2f * z); t0 += z * a2.y;
                z = h1.x + hd.x; z = fmaxf(z, 0.2f * z); t1  = z * a2.x;
                z = h1.y + hd.y; z = fmaxf(z, 0.2f * z); t1 += z * a2.y;
                z = h2.x + hd.x; z = fmaxf(z, 0.2f * z); t2  = z * a2.x;
                z = h2.y + hd.y; z = fmaxf(z, 0.2f * z); t2 += z * a2.y;
                z = h3.x + hd.x; z = fmaxf(z, 0.2f * z); t3  = z * a2.x;
                z = h3.y + hd.y; z = fmaxf(z, 0.2f * z); t3 += z * a2.y;

                t0 += __shfl_xor_sync(0xffffffffu, t0, 1);
                t1 += __shfl_xor_sync(0xffffffffu, t1, 1);
                t2 += __shfl_xor_sync(0xffffffffu, t2, 1);
                t3 += __shfl_xor_sync(0xffffffffu, t3, 1);
                t0 += __shfl_xor_sync(0xffffffffu, t0, 2);
                t1 += __shfl_xor_sync(0xffffffffu, t1, 2);
                t2 += __shfl_xor_sync(0xffffffffu, t2, 2);
                t3 += __shfl_xor_sync(0xffffffffu, t3, 2);
                t0 += __shfl_xor_sync(0xffffffffu, t0, 4);
                t1 += __shfl_xor_sync(0xffffffffu, t1, 4);
                t2 += __shfl_xor_sync(0xffffffffu, t2, 4);
                t3 += __shfl_xor_sync(0xffffffffu, t3, 4);

                float e0 = __expf(t0);
                float e1 = v1 ? __expf(t1) : 0.f;
                float e2 = v2 ? __expf(t2) : 0.f;
                float e3 = v3 ? __expf(t3) : 0.f;

                s += (e0 + e1) + (e2 + e3);
                ax = fmaf(e0, h0.x, fmaf(e1, h1.x, fmaf(e2, h2.x, fmaf(e3, h3.x, ax))));
                ay = fmaf(e0, h0.y, fmaf(e1, h1.y, fmaf(e2, h2.y, fmaf(e3, h3.y, ay))));
            }
        }
        float inv_s = 1.f / s;
        accx = fmaf(ax, inv_s, accx);
        accy = fmaf(ay, inv_s, accy);
    }

    float ox = accx * (1.f / 3.f); ox = ox > 0.f ? ox : 0.f;
    float oy = accy * (1.f / 3.f); oy = oy > 0.f ? oy : 0.f;
    float2 o = {ox, oy};
    *(float2*)&d_h[((size_t)j * n + dst) * HID + l2] = o;
}

// ---------------- pooling (R1-proven form) ----------------
__global__ void k_pool(const int* __restrict__ b0, const int* __restrict__ b1,
                       const int* __restrict__ b2, int n)
{
    const int CH = 128;
    int m = blockIdx.y;
    const int* batch = (m == 0) ? b0 : (m == 1) ? b1 : b2;
    const float* h = d_h + (size_t)m * n * HID;
    int i0 = blockIdx.x * CH;
    int c = threadIdx.x;
    int end = min(i0 + CH, n);
    float acc = 0.f; int cur = -1; int run = 0;
    for (int i = i0; i < end; i++) {
        int bg = batch[i];
        if (bg != cur) {
            if (cur >= 0) {
                atomicAdd(&d_pool[cur * HID + c], acc);
                if (c == 0) atomicAdd(&d_cnt[cur], (float)run);
            }
            cur = bg; acc = 0.f; run = 0;
        }
        acc += h[(size_t)i * HID + c];
        run++;
    }
    if (cur >= 0) {
        atomicAdd(&d_pool[cur * HID + c], acc);
        if (c == 0) atomicAdd(&d_cnt[cur], (float)run);
    }
}

// ---------------- readout MLP (R1-proven form) ----------------
__global__ void k_mlp(const float* __restrict__ Wf1, const float* __restrict__ bf1,
                      const float* __restrict__ Wf2, const float* __restrict__ bf2,
                      const float* __restrict__ Wf3, const float* __restrict__ bf3,
                      float* __restrict__ out)
{
    int g = threadIdx.x; // 256 threads, 1 block
    float inv = 1.f / fmaxf(d_cnt[g], 1.f);
    float y1[16];
    #pragma unroll
    for (int j = 0; j < 16; j++) y1[j] = bf1[j];
    for (int k = 0; k < HID; k++) {
        float v = d_pool[g * HID + k] * inv;
        #pragma unroll
        for (int j = 0; j < 16; j++) y1[j] = fmaf(v, Wf1[k * 16 + j], y1[j]);
    }
    float y2[16];
    #pragma unroll
    for (int j = 0; j < 16; j++) y2[j] = bf2[j];
    #pragma unroll
    for (int k = 0; k < 16; k++) {
        float v = y1[k] > 0.f ? y1[k] : 0.f;
        #pragma unroll
        for (int j = 0; j < 16; j++) y2[j] = fmaf(v, Wf2[k * 16 + j], y2[j]);
    }
    float o = bf3[0];
    #pragma unroll
    for (int j = 0; j < 16; j++) {
        float v = y2[j] > 0.f ? y2[j] : 0.f;
        o = fmaf(v, Wf3[j], o);
    }
    out[g] = o;
}

// ---------------- host launcher ----------------
extern "C" void kernel_launch(void* const* d_in, const int* in_sizes, int n_in,
                              void* d_out, int out_size)
{
    const float *x_text = 0, *x_audio = 0, *x_video = 0;
    const float *Wi_text = 0, *Wi_audio = 0, *Wi_video = 0;
    const float *bi[3] = {0, 0, 0};
    const float *Wn = 0, *bn = 0, *att = 0;
    const float *Wf1 = 0, *bf1 = 0, *Wf2 = 0, *bf2 = 0, *Wf3 = 0, *bf3 = 0;
    const int *batch[3] = {0, 0, 0};
    const int *edges = 0;
    int nb = 0, nbi = 0, n16 = 0;

    for (int i = 0; i < n_in; i++) {
        int s = in_sizes[i];
        const void* p = d_in[i];
        if      (s == 50000 * 300) x_text  = (const float*)p;
        else if (s == 50000 * 74)  x_audio = (const float*)p;
        else if (s == 50000 * 35)  x_video = (const float*)p;
        else if (s == 50000)       { if (nb < 3) batch[nb++] = (const int*)p; }
        else if (s == 9 * 2 * 250000) edges = (const int*)p;
        else if (s == 300 * 64)    Wi_text  = (const float*)p;
        else if (s == 74 * 64)     Wi_audio = (const float*)p;
        else if (s == 35 * 64)     Wi_video = (const float*)p;
        else if (s == 64)          { if (nbi < 3) bi[nbi++] = (const float*)p; }
        else if (s == 2 * 3 * 64 * 64) Wn = (const float*)p;
        else if (s == 2 * 3 * 64)  bn  = (const float*)p;
        else if (s == 2 * 9 * 64)  att = (const float*)p;
        else if (s == 64 * 16)     Wf1 = (const float*)p;
        else if (s == 16)          { if (n16 == 0) bf1 = (const float*)p;
                                     else if (n16 == 1) bf2 = (const float*)p;
                                     else Wf3 = (const float*)p; n16++; }
        else if (s == 16 * 16)     Wf2 = (const float*)p;
        else if (s == 1)           bf3 = (const float*)p;
    }

    const int n = MAXN, E = MAXE;
    const int nblk32 = (n + 31) / 32;

    // Keep k_inproj<300> in the ncu capture slot (4th launch) to verify the delta.
    k_init<<<(TOTDEG + 255) / 256, 256>>>();                                          // 1
    k_start_min<<<dim3((n + 255) / 256, 3), 256>>>(batch[0], batch[1], batch[2], n);  // 2
    k_hist<<<dim3((E + 255) / 256, 9), 256>>>(edges, E);                              // 3
    k_inproj<300, 30><<<nblk32, 128>>>(x_text,  Wi_text,  bi[0], batch[0], 0, n);     // 4 <- ncu slot
    k_inproj<74, 37> <<<nblk32, 128>>>(x_audio, Wi_audio, bi[1], batch[1], 1, n);     // 5
    k_inproj<35, 35> <<<nblk32, 128>>>(x_video, Wi_video, bi[2], batch[2], 2, n);     // 6

    // CSR build (independent of projections)
    k_scanA<<<SCAN_BLOCKS, 256>>>();
    k_scanB<<<1, 256>>>();
    k_scanC<<<(TOTDEG + 255) / 256, 256>>>();
    k_scatter<<<dim3((E + 255) / 256, 9), 256>>>(edges, E);

    // GAT layers
    for (int l = 0; l < 2; l++) {
        k_nodeproj<<<dim3(nblk32, 3), 256>>>(Wn + (size_t)l * 3 * HID * HID,
                                             bn + (size_t)l * 3 * HID, n);
        k_gat<<<dim3((n + 7) / 8, 3), 256>>>(att + (size_t)l * 9 * HID, n);
    }

    // pooling + MLP head
    k_pool<<<dim3((n + 127) / 128, 3), 64>>>(batch[0], batch[1], batch[2], n);
    k_mlp<<<1, 256>>>(Wf1, bf1, Wf2, bf2, Wf3, bf3, (float*)d_out);
}

// round 17
// speedup vs baseline: 1.1750x; 1.0628x over previous
#include <cuda_runtime.h>

#define MODS   3
#define HEADS  4
#define HID    64
#define G      256
#define MAXN   50000
#define MAXE   250000
#define TOTDEG (9 * MAXN)
#define SCAN_BLOCKS ((TOTDEG + 2047) / 2048)   // 220

// ---------------- scratch (device globals; no allocation allowed) ----------------
static __device__ __align__(256) float d_h  [MODS * MAXN * HID];  // layer features
static __device__ __align__(256) float d_hp [MODS * MAXN * HID];  // projected features
static __device__ __align__(16) int   d_deg    [TOTDEG];
static __device__ __align__(16) int   d_scantmp[TOTDEG];
static __device__ int   d_bsum  [SCAN_BLOCKS];
static __device__ int   d_rowptr[9 * (MAXN + 1)];
static __device__ int   d_cursor[9 * MAXN];
static __device__ int   d_esrc  [9 * MAXE];
static __device__ int   d_start [MODS * G];
static __device__ float d_pool  [G * HID];
static __device__ float d_cnt   [G];

// ---------------- init ----------------
__global__ void k_init()
{
    int i = blockIdx.x * blockDim.x + threadIdx.x;
    if (i < TOTDEG)   d_deg[i] = 0;
    if (i < MODS * G) d_start[i] = 0x7fffffff;
    if (i < G * HID)  d_pool[i] = 0.f;
    if (i < G)        d_cnt[i] = 0.f;
    if (i < 9)        d_rowptr[i * (MAXN + 1) + MAXN] = MAXE;
}

__global__ void k_start_min(const int* __restrict__ b0, const int* __restrict__ b1,
                            const int* __restrict__ b2, int n)
{
    int i = blockIdx.x * blockDim.x + threadIdx.x;
    if (i >= n) return;
    const int* b = (blockIdx.y == 0) ? b0 : (blockIdx.y == 1) ? b1 : b2;
    atomicMin(&d_start[blockIdx.y * G + b[i]], i);
}

// ---------------- CSR build ----------------
__global__ void k_hist(const int* __restrict__ edges, int E)
{
    int rel = blockIdx.y;
    int e = blockIdx.x * blockDim.x + threadIdx.x;
    if (e >= E) return;
    int dN = edges[(size_t)rel * 2 * E + E + e];
    atomicAdd(&d_deg[rel * MAXN + dN], 1);
}

__global__ void k_scanA()
{
    __shared__ int sh[256];
    int t = threadIdx.x;
    int base = blockIdx.x * 2048 + t * 8;
    int v0 = 0, v1 = 0, v2 = 0, v3 = 0, v4 = 0, v5 = 0, v6 = 0, v7 = 0;
    if (base + 7 < TOTDEG) {
        int4 a = *(const int4*)&d_deg[base];
        int4 b = *(const int4*)&d_deg[base + 4];
        v0 = a.x; v1 = a.y; v2 = a.z; v3 = a.w;
        v4 = b.x; v5 = b.y; v6 = b.z; v7 = b.w;
    } else {
        if (base + 0 < TOTDEG) v0 = d_deg[base + 0];
        if (base + 1 < TOTDEG) v1 = d_deg[base + 1];
        if (base + 2 < TOTDEG) v2 = d_deg[base + 2];
        if (base + 3 < TOTDEG) v3 = d_deg[base + 3];
        if (base + 4 < TOTDEG) v4 = d_deg[base + 4];
        if (base + 5 < TOTDEG) v5 = d_deg[base + 5];
        if (base + 6 < TOTDEG) v6 = d_deg[base + 6];
        if (base + 7 < TOTDEG) v7 = d_deg[base + 7];
    }
    int tsum = v0 + v1 + v2 + v3 + v4 + v5 + v6 + v7;
    sh[t] = tsum;
    __syncthreads();
    for (int off = 1; off < 256; off <<= 1) {
        int v = (t >= off) ? sh[t - off] : 0;
        __syncthreads();
        sh[t] += v;
        __syncthreads();
    }
    int run = sh[t] - tsum;
    if (t == 255) d_bsum[blockIdx.x] = sh[255];
    int w;
    w = run; run += v0; if (base + 0 < TOTDEG) d_scantmp[base + 0] = w;
    w = run; run += v1; if (base + 1 < TOTDEG) d_scantmp[base + 1] = w;
    w = run; run += v2; if (base + 2 < TOTDEG) d_scantmp[base + 2] = w;
    w = run; run += v3; if (base + 3 < TOTDEG) d_scantmp[base + 3] = w;
    w = run; run += v4; if (base + 4 < TOTDEG) d_scantmp[base + 4] = w;
    w = run; run += v5; if (base + 5 < TOTDEG) d_scantmp[base + 5] = w;
    w = run; run += v6; if (base + 6 < TOTDEG) d_scantmp[base + 6] = w;
    w = run; run += v7; if (base + 7 < TOTDEG) d_scantmp[base + 7] = w;
}

__global__ void k_scanB()
{
    __shared__ int sh[256];
    int t = threadIdx.x;
    int v = (t < SCAN_BLOCKS) ? d_bsum[t] : 0;
    sh[t] = v;
    __syncthreads();
    for (int off = 1; off < 256; off <<= 1) {
        int x = (t >= off) ? sh[t - off] : 0;
        __syncthreads();
        sh[t] += x;
        __syncthreads();
    }
    if (t < SCAN_BLOCKS) d_bsum[t] = sh[t] - v;
}

__global__ void k_scanC()
{
    int idx = blockIdx.x * blockDim.x + threadIdx.x;
    if (idx >= TOTDEG) return;
    int val = d_scantmp[idx] + d_bsum[idx >> 11];
    int rel = idx / MAXN;
    int loc = idx - rel * MAXN;
    int r = val - rel * MAXE;
    d_rowptr[rel * (MAXN + 1) + loc] = r;
    d_cursor[rel * MAXN + loc] = r;
}

__global__ void k_scatter(const int* __restrict__ edges, int E)
{
    int rel = blockIdx.y;
    int e = blockIdx.x * blockDim.x + threadIdx.x;
    if (e >= E) return;
    const int* src = edges + (size_t)rel * 2 * E;
    int sN = src[e], dN = src[E + e];
    int pos = atomicAdd(&d_cursor[rel * MAXN + dN], 1);
    d_esrc[(size_t)rel * E + pos] = sN;
}

// ---------------- input projection + PE ----------------
// 256 thr, 64 nodes/block, 4 nodes x 4 cols/thread; xs AND Ws staged per k-chunk
// so smem stays ~16KB -> high occupancy, while keeping 2 B/FMA smem traffic
// (R15/R16 established: L1-bound scales with smem bytes/FMA; R16 showed the
// tile needs >=48 warps/SM to hide latency).
template<int IN, int CK>
__global__ void k_inproj(const float* __restrict__ x, const float* __restrict__ W,
                         const float* __restrict__ b, const int* __restrict__ batch,
                         int mod, int n)
{
    __shared__ float  xs[64][CK];
    __shared__ float4 Ws[CK * 16];
    int tid = threadIdx.x;   // 256 threads
    int node0 = blockIdx.x * 64;
    int ty = tid >> 4, tx = tid & 15;   // ty 0..15 (4 nodes each), tx 0..15 (4 cols)
    int nbase = node0 + ty * 4;

    const float4* __restrict__ W4 = (const float4*)W;
    float4 bb = ((const float4*)b)[tx];
    float4 acc0 = bb, acc1 = bb, acc2 = bb, acc3 = bb;
    const float* x0 = xs[ty * 4 + 0];
    const float* x1 = xs[ty * 4 + 1];
    const float* x2 = xs[ty * 4 + 2];
    const float* x3 = xs[ty * 4 + 3];

    const int NCHUNK = IN / CK;
    for (int ch = 0; ch < NCHUNK; ch++) {
        int k0 = ch * CK;
        if (ch) __syncthreads();          // protect previous chunk's xs/Ws reads
        for (int idx = tid; idx < 64 * CK; idx += 256) {
            int r = idx / CK, c = idx - r * CK;
            int node = node0 + r;
            xs[r][c] = (node < n) ? x[(size_t)node * IN + k0 + c] : 0.f;
        }
        for (int idx = tid; idx < CK * 16; idx += 256)
            Ws[idx] = W4[(size_t)k0 * 16 + idx];
        __syncthreads();
        #pragma unroll 5
        for (int c = 0; c < CK; c++) {
            float4 wv = Ws[c * 16 + tx];
            float v0 = x0[c], v1 = x1[c], v2 = x2[c], v3 = x3[c];
            acc0.x = fmaf(v0, wv.x, acc0.x); acc0.y = fmaf(v0, wv.y, acc0.y);
            acc0.z = fmaf(v0, wv.z, acc0.z); acc0.w = fmaf(v0, wv.w, acc0.w);
            acc1.x = fmaf(v1, wv.x, acc1.x); acc1.y = fmaf(v1, wv.y, acc1.y);
            acc1.z = fmaf(v1, wv.z, acc1.z); acc1.w = fmaf(v1, wv.w, acc1.w);
            acc2.x = fmaf(v2, wv.x, acc2.x); acc2.y = fmaf(v2, wv.y, acc2.y);
            acc2.z = fmaf(v2, wv.z, acc2.z); acc2.w = fmaf(v2, wv.w, acc2.w);
            acc3.x = fmaf(v3, wv.x, acc3.x); acc3.y = fmaf(v3, wv.y, acc3.y);
            acc3.z = fmaf(v3, wv.z, acc3.z); acc3.w = fmaf(v3, wv.w, acc3.w);
        }
    }

    // positional encoding (R1-proven math); cols tx*4 .. tx*4+3 -> kk = 2tx, 2tx+1
    float div0 = expf(-(float)(2 * (2 * tx)) * (9.210340371976184f / 64.0f));
    float div1 = expf(-(float)(2 * (2 * tx + 1)) * (9.210340371976184f / 64.0f));
    #pragma unroll
    for (int q = 0; q < 4; q++) {
        int node = nbase + q;
        if (node >= n) break;
        float4 acc = (q == 0) ? acc0 : (q == 1) ? acc1 : (q == 2) ? acc2 : acc3;
        float pf = (float)(node - d_start[mod * G + batch[node]]);
        float a0 = pf * div0, a1 = pf * div1;
        acc.x += sinf(a0); acc.y += cosf(a0);
        acc.z += sinf(a1); acc.w += cosf(a1);
        ((float4*)(d_h + ((size_t)mod * n + node) * HID))[tx] = acc;
    }
}

// ---------------- node projection: W staged in smem, 2 nodes x 4 cols per thread (R8/R14-proven) ----------------
__global__ void k_nodeproj(const float* __restrict__ Wl, const float* __restrict__ bl, int n)
{
    __shared__ float4 Ws[HID * 16];     // 16KB
    __shared__ float  xs[32][HID];      // 8KB
    int m = blockIdx.y;
    int tid = threadIdx.x;
    int node0 = blockIdx.x * 32;
    const float4* __restrict__ W4 = (const float4*)(Wl + m * HID * HID);
    for (int idx = tid; idx < HID * 16; idx += 256) Ws[idx] = W4[idx];
    const float* __restrict__ src = d_h + (size_t)m * n * HID;
    for (int idx = tid; idx < 32 * HID; idx += 256) {
        int r = idx >> 6, k = idx & 63;
        int node = node0 + r;
        xs[r][k] = (node < n) ? src[(size_t)node * HID + k] : 0.f;
    }
    __syncthreads();
    int ty = tid >> 4, tx = tid & 15;
    int na = node0 + ty * 2, nb = na + 1;

    float4 bb = ((const float4*)(bl + m * HID))[tx];
    float4 acc0 = bb, acc1 = bb;
    const float* xa = xs[ty * 2];
    const float* xb = xs[ty * 2 + 1];
    #pragma unroll 4
    for (int k = 0; k < HID; k++) {
        float4 wv = Ws[k * 16 + tx];
        float va = xa[k], vb = xb[k];
        acc0.x = fmaf(va, wv.x, acc0.x);
        acc0.y = fmaf(va, wv.y, acc0.y);
        acc0.z = fmaf(va, wv.z, acc0.z);
        acc0.w = fmaf(va, wv.w, acc0.w);
        acc1.x = fmaf(vb, wv.x, acc1.x);
        acc1.y = fmaf(vb, wv.y, acc1.y);
        acc1.z = fmaf(vb, wv.z, acc1.z);
        acc1.w = fmaf(vb, wv.w, acc1.w);
    }
    if (na < n) ((float4*)(d_hp + ((size_t)m * n + na) * HID))[tx] = acc0;
    if (nb < n) ((float4*)(d_hp + ((size_t)m * n + nb) * HID))[tx] = acc1;
}

// ---------------- GAT layer: warp per dst; 4 edges in flight (MLP=4) ----------------
__global__ void k_gat(const float* __restrict__ attL, int n)
{
    int wid = threadIdx.x >> 5, lane = threadIdx.x & 31;
    int dst = blockIdx.x * 8 + wid;
    if (dst >= n) return;
    int j = blockIdx.y;
    int l2 = lane * 2;

    float2 hd = *(const float2*)&d_hp[((size_t)j * n + dst) * HID + l2];
    float accx = 0.f, accy = 0.f;

    for (int i = 0; i < MODS; i++) {
        int rel = i * 3 + j;
        int rs = d_rowptr[rel * (MAXN + 1) + dst];
        int re = d_rowptr[rel * (MAXN + 1) + dst + 1];
        if (rs == re) continue;
        float2 a2 = *(const float2*)&attL[rel * HID + l2];
        const float* __restrict__ hpB = d_hp + (size_t)i * n * HID;
        const int* __restrict__ es = d_esrc + (size_t)rel * MAXE;

        float s = 0.f, ax = 0.f, ay = 0.f;
        for (int c0 = rs; c0 < re; c0 += 32) {
            int idx = c0 + lane;
            int my = es[idx < re ? idx : re - 1];   // clamped: always a valid src
            int cnt = min(32, re - c0);
            for (int q = 0; q < cnt; q += 4) {
                int s0 = __shfl_sync(0xffffffffu, my, q);
                int s1 = __shfl_sync(0xffffffffu, my, q + 1);
                int s2 = __shfl_sync(0xffffffffu, my, q + 2);
                int s3 = __shfl_sync(0xffffffffu, my, q + 3);
                bool v1 = (q + 1 < cnt), v2 = (q + 2 < cnt), v3 = (q + 3 < cnt);
                float2 h0 = *(const float2*)&hpB[(size_t)s0 * HID + l2];
                float2 h1 = *(const float2*)&hpB[(size_t)s1 * HID + l2];
                float2 h2 = *(const float2*)&hpB[(size_t)s2 * HID + l2];
                float2 h3 = *(const float2*)&hpB[(size_t)s3 * HID + l2];

                float z, t0, t1, t2, t3;
                z = h0.x + hd.x; z = fmaxf(z, 0.2f * z); t0  = z * a2.x;
                z = h0.y + hd.y; z = fmaxf(z, 0.2f * z); t0 += z * a2.y;
                z = h1.x + hd.x; z = fmaxf(z, 0.2f * z); t1  = z * a2.x;
                z = h1.y + hd.y; z = fmaxf(z, 0.2f * z); t1 += z * a2.y;
                z = h2.x + hd.x; z = fmaxf(z, 0.2f * z); t2  = z * a2.x;
                z = h2.y + hd.y; z = fmaxf(z, 0.2f * z); t2 += z * a2.y;
                z = h3.x + hd.x; z = fmaxf(z, 0.2f * z); t3  = z * a2.x;
                z = h3.y + hd.y; z = fmaxf(z, 0.2f * z); t3 += z * a2.y;

                t0 += __shfl_xor_sync(0xffffffffu, t0, 1);
                t1 += __shfl_xor_sync(0xffffffffu, t1, 1);
                t2 += __shfl_xor_sync(0xffffffffu, t2, 1);
                t3 += __shfl_xor_sync(0xffffffffu, t3, 1);
                t0 += __shfl_xor_sync(0xffffffffu, t0, 2);
                t1 += __shfl_xor_sync(0xffffffffu, t1, 2);
                t2 += __shfl_xor_sync(0xffffffffu, t2, 2);
                t3 += __shfl_xor_sync(0xffffffffu, t3, 2);
                t0 += __shfl_xor_sync(0xffffffffu, t0, 4);
                t1 += __shfl_xor_sync(0xffffffffu, t1, 4);
                t2 += __shfl_xor_sync(0xffffffffu, t2, 4);
                t3 += __shfl_xor_sync(0xffffffffu, t3, 4);

                float e0 = __expf(t0);
                float e1 = v1 ? __expf(t1) : 0.f;
                float e2 = v2 ? __expf(t2) : 0.f;
                float e3 = v3 ? __expf(t3) : 0.f;

                s += (e0 + e1) + (e2 + e3);
                ax = fmaf(e0, h0.x, fmaf(e1, h1.x, fmaf(e2, h2.x, fmaf(e3, h3.x, ax))));
                ay = fmaf(e0, h0.y, fmaf(e1, h1.y, fmaf(e2, h2.y, fmaf(e3, h3.y, ay))));
            }
        }
        float inv_s = 1.f / s;
        accx = fmaf(ax, inv_s, accx);
        accy = fmaf(ay, inv_s, accy);
    }

    float ox = accx * (1.f / 3.f); ox = ox > 0.f ? ox : 0.f;
    float oy = accy * (1.f / 3.f); oy = oy > 0.f ? oy : 0.f;
    float2 o = {ox, oy};
    *(float2*)&d_h[((size_t)j * n + dst) * HID + l2] = o;
}

// ---------------- pooling (R1-proven form) ----------------
__global__ void k_pool(const int* __restrict__ b0, const int* __restrict__ b1,
                       const int* __restrict__ b2, int n)
{
    const int CH = 128;
    int m = blockIdx.y;
    const int* batch = (m == 0) ? b0 : (m == 1) ? b1 : b2;
    const float* h = d_h + (size_t)m * n * HID;
    int i0 = blockIdx.x * CH;
    int c = threadIdx.x;
    int end = min(i0 + CH, n);
    float acc = 0.f; int cur = -1; int run = 0;
    for (int i = i0; i < end; i++) {
        int bg = batch[i];
        if (bg != cur) {
            if (cur >= 0) {
                atomicAdd(&d_pool[cur * HID + c], acc);
                if (c == 0) atomicAdd(&d_cnt[cur], (float)run);
            }
            cur = bg; acc = 0.f; run = 0;
        }
        acc += h[(size_t)i * HID + c];
        run++;
    }
    if (cur >= 0) {
        atomicAdd(&d_pool[cur * HID + c], acc);
        if (c == 0) atomicAdd(&d_cnt[cur], (float)run);
    }
}

// ---------------- readout MLP (R1-proven form) ----------------
__global__ void k_mlp(const float* __restrict__ Wf1, const float* __restrict__ bf1,
                      const float* __restrict__ Wf2, const float* __restrict__ bf2,
                      const float* __restrict__ Wf3, const float* __restrict__ bf3,
                      float* __restrict__ out)
{
    int g = threadIdx.x; // 256 threads, 1 block
    float inv = 1.f / fmaxf(d_cnt[g], 1.f);
    float y1[16];
    #pragma unroll
    for (int j = 0; j < 16; j++) y1[j] = bf1[j];
    for (int k = 0; k < HID; k++) {
        float v = d_pool[g * HID + k] * inv;
        #pragma unroll
        for (int j = 0; j < 16; j++) y1[j] = fmaf(v, Wf1[k * 16 + j], y1[j]);
    }
    float y2[16];
    #pragma unroll
    for (int j = 0; j < 16; j++) y2[j] = bf2[j];
    #pragma unroll
    for (int k = 0; k < 16; k++) {
        float v = y1[k] > 0.f ? y1[k] : 0.f;
        #pragma unroll
        for (int j = 0; j < 16; j++) y2[j] = fmaf(v, Wf2[k * 16 + j], y2[j]);
    }
    float o = bf3[0];
    #pragma unroll
    for (int j = 0; j < 16; j++) {
        float v = y2[j] > 0.f ? y2[j] : 0.f;
        o = fmaf(v, Wf3[j], o);
    }
    out[g] = o;
}

// ---------------- host launcher ----------------
extern "C" void kernel_launch(void* const* d_in, const int* in_sizes, int n_in,
                              void* d_out, int out_size)
{
    const float *x_text = 0, *x_audio = 0, *x_video = 0;
    const float *Wi_text = 0, *Wi_audio = 0, *Wi_video = 0;
    const float *bi[3] = {0, 0, 0};
    const float *Wn = 0, *bn = 0, *att = 0;
    const float *Wf1 = 0, *bf1 = 0, *Wf2 = 0, *bf2 = 0, *Wf3 = 0, *bf3 = 0;
    const int *batch[3] = {0, 0, 0};
    const int *edges = 0;
    int nb = 0, nbi = 0, n16 = 0;

    for (int i = 0; i < n_in; i++) {
        int s = in_sizes[i];
        const void* p = d_in[i];
        if      (s == 50000 * 300) x_text  = (const float*)p;
        else if (s == 50000 * 74)  x_audio = (const float*)p;
        else if (s == 50000 * 35)  x_video = (const float*)p;
        else if (s == 50000)       { if (nb < 3) batch[nb++] = (const int*)p; }
        else if (s == 9 * 2 * 250000) edges = (const int*)p;
        else if (s == 300 * 64)    Wi_text  = (const float*)p;
        else if (s == 74 * 64)     Wi_audio = (const float*)p;
        else if (s == 35 * 64)     Wi_video = (const float*)p;
        else if (s == 64)          { if (nbi < 3) bi[nbi++] = (const float*)p; }
        else if (s == 2 * 3 * 64 * 64) Wn = (const float*)p;
        else if (s == 2 * 3 * 64)  bn  = (const float*)p;
        else if (s == 2 * 9 * 64)  att = (const float*)p;
        else if (s == 64 * 16)     Wf1 = (const float*)p;
        else if (s == 16)          { if (n16 == 0) bf1 = (const float*)p;
                                     else if (n16 == 1) bf2 = (const float*)p;
                                     else Wf3 = (const float*)p; n16++; }
        else if (s == 16 * 16)     Wf2 = (const float*)p;
        else if (s == 1)           bf3 = (const float*)p;
    }

    const int n = MAXN, E = MAXE;
    const int nblk32 = (n + 31) / 32;
    const int nblk64 = (n + 63) / 64;

    // Keep k_inproj<300> in the ncu capture slot (4th launch) to verify the delta.
    k_init<<<(TOTDEG + 255) / 256, 256>>>();                                          // 1
    k_start_min<<<dim3((n + 255) / 256, 3), 256>>>(batch[0], batch[1], batch[2], n);  // 2
    k_hist<<<dim3((E + 255) / 256, 9), 256>>>(edges, E);                              // 3
    k_inproj<300, 30><<<nblk64, 256>>>(x_text,  Wi_text,  bi[0], batch[0], 0, n);     // 4 <- ncu slot
    k_inproj<74, 37> <<<nblk64, 256>>>(x_audio, Wi_audio, bi[1], batch[1], 1, n);     // 5
    k_inproj<35, 35> <<<nblk64, 256>>>(x_video, Wi_video, bi[2], batch[2], 2, n);     // 6

    // CSR build (independent of projections)
    k_scanA<<<SCAN_BLOCKS, 256>>>();
    k_scanB<<<1, 256>>>();
    k_scanC<<<(TOTDEG + 255) / 256, 256>>>();
    k_scatter<<<dim3((E + 255) / 256, 9), 256>>>(edges, E);

    // GAT layers
    for (int l = 0; l < 2; l++) {
        k_nodeproj<<<dim3(nblk32, 3), 256>>>(Wn + (size_t)l * 3 * HID * HID,
                                             bn + (size_t)l * 3 * HID, n);
        k_gat<<<dim3((n + 7) / 8, 3), 256>>>(att + (size_t)l * 9 * HID, n);
    }

    // pooling + MLP head
    k_pool<<<dim3((n + 127) / 128, 3), 64>>>(batch[0], batch[1], batch[2], n);
    k_mlp<<<1, 256>>>(Wf1, bf1, Wf2, bf2, Wf3, bf3, (float*)d_out);
}